// round 3
// baseline (speedup 1.0000x reference)
#include <cuda_runtime.h>
#include <cstdint>
#include <math.h>

// N=4, S=4096, E=1024, H=16, D=64
// 4 GEMMs of [16384,1024] x [1024,1024]^T (+bias), plus per-position 16x16
// head-gram softmax with the reference's scrambled reshape folded into the
// attention store.

// Scratch (alloc-guard compliant: __device__ globals, 4 x 64MB)
__device__ float g_Q[16777216];
__device__ float g_K[16777216];
__device__ float g_V[16777216];
__device__ float g_O[16777216];

__device__ __forceinline__ uint32_t f2tf32(float f) {
    uint32_t u;
    asm("cvt.rna.tf32.f32 %0, %1;" : "=r"(u) : "f"(f));
    return u;
}

// ---------------------------------------------------------------------------
// GEMM: C[16384,1024] = A[16384,1024] @ B[1024,1024]^T + bias
// Block tile 128x128, K-tile 32, 256 threads (8 warps, 2Mx4N warp grid),
// warp tile 64x32 via tf32 mma.sync.m16n8k8 (4x4 atoms).
// smem pitch 36 floats: 16B-aligned float4 stores AND conflict-free fragment
// reads ((36*r + c) mod 32 covers all banks for r in 0..7, c in 0..3).
// ---------------------------------------------------------------------------
__global__ __launch_bounds__(256, 2)
void gemm_tn_bias(const float* __restrict__ A, const float* __restrict__ B,
                  const float* __restrict__ bias, float* __restrict__ C) {
    __shared__ __align__(16) float As[128][36];
    __shared__ __align__(16) float Bs[128][36];

    const int tid  = threadIdx.x;
    const int warp = tid >> 5;
    const int lane = tid & 31;
    const int wm = (warp & 1) * 64;   // warp M offset
    const int wn = (warp >> 1) * 32;  // warp N offset
    const int r  = lane >> 2;
    const int cx = lane & 3;

    const float* Ab = A + (size_t)blockIdx.y * 128 * 1024;
    const float* Bb = B + (size_t)blockIdx.x * 128 * 1024;

    float acc[4][4][4];
#pragma unroll
    for (int i = 0; i < 4; i++)
#pragma unroll
        for (int j = 0; j < 4; j++)
#pragma unroll
            for (int k = 0; k < 4; k++) acc[i][j][k] = 0.f;

    for (int kt = 0; kt < 32; kt++) {
        const int kb = kt * 32;
        // Load 128x32 A-tile and B-tile (coalesced float4)
#pragma unroll
        for (int i = 0; i < 4; i++) {
            int idx = tid + i * 256;       // 0..1023
            int row = idx >> 3;
            int c4  = (idx & 7) * 4;
            *(float4*)&As[row][c4] = *(const float4*)(Ab + (size_t)row * 1024 + kb + c4);
            *(float4*)&Bs[row][c4] = *(const float4*)(Bb + (size_t)row * 1024 + kb + c4);
        }
        __syncthreads();

#pragma unroll
        for (int ks = 0; ks < 4; ks++) {
            const int k0 = ks * 8;
            uint32_t a[4][4];
#pragma unroll
            for (int am = 0; am < 4; am++) {
                const int m0 = wm + am * 16;
                a[am][0] = f2tf32(As[m0 + r][k0 + cx]);
                a[am][1] = f2tf32(As[m0 + r + 8][k0 + cx]);
                a[am][2] = f2tf32(As[m0 + r][k0 + cx + 4]);
                a[am][3] = f2tf32(As[m0 + r + 8][k0 + cx + 4]);
            }
            uint32_t b[4][2];
#pragma unroll
            for (int bn = 0; bn < 4; bn++) {
                const int n0 = wn + bn * 8;
                b[bn][0] = f2tf32(Bs[n0 + r][k0 + cx]);
                b[bn][1] = f2tf32(Bs[n0 + r][k0 + cx + 4]);
            }
#pragma unroll
            for (int am = 0; am < 4; am++)
#pragma unroll
                for (int bn = 0; bn < 4; bn++)
                    asm volatile(
                        "mma.sync.aligned.m16n8k8.row.col.f32.tf32.tf32.f32 "
                        "{%0,%1,%2,%3}, {%4,%5,%6,%7}, {%8,%9}, {%0,%1,%2,%3};\n"
                        : "+f"(acc[am][bn][0]), "+f"(acc[am][bn][1]),
                          "+f"(acc[am][bn][2]), "+f"(acc[am][bn][3])
                        : "r"(a[am][0]), "r"(a[am][1]), "r"(a[am][2]), "r"(a[am][3]),
                          "r"(b[bn][0]), "r"(b[bn][1]));
        }
        __syncthreads();
    }

    // Epilogue: bias add + float2 stores
    const int rowBase = blockIdx.y * 128 + wm + r;
    const int colBase = blockIdx.x * 128 + wn;
#pragma unroll
    for (int bn = 0; bn < 4; bn++) {
        const int col = colBase + bn * 8 + cx * 2;
        const float b0 = bias[col];
        const float b1 = bias[col + 1];
#pragma unroll
        for (int am = 0; am < 4; am++) {
            const int row = rowBase + am * 16;
            float2 v;
            v.x = acc[am][bn][0] + b0;
            v.y = acc[am][bn][1] + b1;
            *(float2*)&C[(size_t)row * 1024 + col] = v;
            v.x = acc[am][bn][2] + b0;
            v.y = acc[am][bn][3] + b1;
            *(float2*)&C[(size_t)(row + 8) * 1024 + col] = v;
        }
    }
}

// ---------------------------------------------------------------------------
// Per-position head-gram attention.
// One block (128 threads) per (n,s) position:
//   G[q,l] = (1/8) * sum_d Q[q*64+d]*K[l*64+d]   (16x16)
//   P = softmax_rows(G)
//   out[h,d] = sum_l P[h,l]*V[l*64+d]
// Store folds reference's (N,H,S,D)->(N,4096,1024) flat reshape:
//   row' = h*256 + s/16, col' = (s%16)*64 + d
// smem pitch 66 => K/V reads across l hit distinct banks (2l mod 32 distinct).
// ---------------------------------------------------------------------------
__global__ __launch_bounds__(128)
void attn_kernel() {
    const int pos = blockIdx.x;          // n*4096 + s
    const int n = pos >> 12;
    const int s = pos & 4095;
    const int tid = threadIdx.x;

    __shared__ float Qs[16 * 66];
    __shared__ float Ks[16 * 66];
    __shared__ float Vs[16 * 66];
    __shared__ float G[16][17];
    __shared__ float P[16][17];

    const float* qrow = g_Q + (size_t)pos * 1024;
    const float* krow = g_K + (size_t)pos * 1024;
    const float* vrow = g_V + (size_t)pos * 1024;

#pragma unroll
    for (int i = tid; i < 1024; i += 128) {
        const int h = i >> 6, d = i & 63;
        Qs[h * 66 + d] = qrow[i];
        Ks[h * 66 + d] = krow[i];
        Vs[h * 66 + d] = vrow[i];
    }
    __syncthreads();

    // 256 gram entries, 2 per thread
#pragma unroll
    for (int e = tid; e < 256; e += 128) {
        const int q = e >> 4, l = e & 15;
        const float* qp = Qs + q * 66;
        const float* kp = Ks + l * 66;
        float acc = 0.f;
#pragma unroll
        for (int d = 0; d < 64; d++) acc = fmaf(qp[d], kp[d], acc);
        G[q][l] = acc * 0.125f;  // 1/sqrt(64)
    }
    __syncthreads();

    // Row softmax (16 rows, one thread each)
    if (tid < 16) {
        float mx = -1e30f;
#pragma unroll
        for (int l = 0; l < 16; l++) mx = fmaxf(mx, G[tid][l]);
        float ex[16];
        float sum = 0.f;
#pragma unroll
        for (int l = 0; l < 16; l++) {
            ex[l] = expf(G[tid][l] - mx);
            sum += ex[l];
        }
        const float inv = 1.0f / sum;
#pragma unroll
        for (int l = 0; l < 16; l++) P[tid][l] = ex[l] * inv;
    }
    __syncthreads();

    // out[h][d0..d0+7], thread t -> h = t/8, d0 = (t%8)*8
    const int h = tid >> 3;
    const int d0 = (tid & 7) * 8;
    float o[8];
#pragma unroll
    for (int j = 0; j < 8; j++) o[j] = 0.f;
#pragma unroll
    for (int l = 0; l < 16; l++) {
        const float p = P[h][l];
        const float* vp = Vs + l * 66 + d0;
#pragma unroll
        for (int j = 0; j < 8; j++) o[j] = fmaf(p, vp[j], o[j]);
    }

    // Scrambled store (reference's flat reshape)
    float* op = g_O + (((size_t)n << 12) + (h << 8) + (s >> 4)) * 1024
                + (s & 15) * 64 + d0;
#pragma unroll
    for (int j = 0; j < 8; j++) op[j] = o[j];
}

// ---------------------------------------------------------------------------
extern "C" void kernel_launch(void* const* d_in, const int* in_sizes, int n_in,
                              void* d_out, int out_size) {
    const float* x  = (const float*)d_in[0];
    const float* Wq = (const float*)d_in[1];
    const float* bq = (const float*)d_in[2];
    const float* Wk = (const float*)d_in[3];
    const float* bk = (const float*)d_in[4];
    const float* Wv = (const float*)d_in[5];
    const float* bv = (const float*)d_in[6];
    const float* Wo = (const float*)d_in[7];
    const float* bo = (const float*)d_in[8];

    float *pQ, *pK, *pV, *pO;
    cudaGetSymbolAddress((void**)&pQ, g_Q);
    cudaGetSymbolAddress((void**)&pK, g_K);
    cudaGetSymbolAddress((void**)&pV, g_V);
    cudaGetSymbolAddress((void**)&pO, g_O);

    dim3 grid(8, 128);   // N-tiles x M-tiles
    dim3 block(256);
    gemm_tn_bias<<<grid, block>>>(x, Wq, bq, pQ);
    gemm_tn_bias<<<grid, block>>>(x, Wk, bk, pK);
    gemm_tn_bias<<<grid, block>>>(x, Wv, bv, pV);
    attn_kernel<<<16384, 128>>>();
    gemm_tn_bias<<<grid, block>>>(pO, Wo, bo, (float*)d_out);
}

// round 11
// speedup vs baseline: 1.7871x; 1.7871x over previous
#include <cuda_runtime.h>
#include <cuda_fp16.h>
#include <cstdint>
#include <math.h>

// N=4, S=4096, E=1024, H=16, D=64
// Pipeline: fp16-convert x,W | 3x fp16 mma.sync GEMM (Q,K,V fp32 out) |
// smem-free head-gram attention (scrambled store, fp16 out) | final GEMM.
// NOTE: tcgen05 is unusable here (harness PTX target is compute_103, not
// compute_103a; ptxas rejects tcgen05.*). Legacy HMMA path only.

// ---------------- scratch (alloc-guard compliant device globals) ----------
__device__ __half g_Xh[16777216];      // x in fp16
__device__ float  g_Q[16777216];
__device__ float  g_K[16777216];
__device__ float  g_V[16777216];
__device__ __half g_Oh[16777216];      // attn out, scrambled, fp16
__device__ __half g_Wh[4194304];       // Wq,Wk,Wv,Wo in fp16

__device__ __forceinline__ uint32_t smem_u32(const void* p) {
    uint32_t a;
    asm("{ .reg .u64 t; cvta.to.shared.u64 t, %1; cvt.u32.u64 %0, t; }"
        : "=r"(a) : "l"(p));
    return a;
}

// ---------------------------------------------------------------------------
// fp16 GEMM: C[16384,1024] = Ah[16384,1024] @ Bh[1024,1024]^T + bias (fp32 acc)
// CTA tile 128x128, BK=32, 4-stage cp.async pipeline, 8 warps (2Mx4N),
// warp tile 64x32, mma.sync.m16n8k16 (4x4 atoms x 2 k-steps per K-tile).
// smem row pitch 80B (40 halfs): 16B-aligned cp.async dsts AND conflict-free
// ldmatrix phases (banks (20r+c) mod 32 all distinct for r in 0..7).
// ---------------------------------------------------------------------------
static constexpr int GH_STAGE_B = 20480;   // (128 A-rows + 128 B-rows) * 80B
static constexpr int GH_SMEM    = 4 * GH_STAGE_B;  // 81920

__global__ __launch_bounds__(256)
void gemm_h(const __half* __restrict__ A, const __half* __restrict__ B,
            const float* __restrict__ bias, float* __restrict__ C) {
    extern __shared__ __align__(128) char smem[];
    const uint32_t sb = smem_u32(smem);
    const int tid = threadIdx.x;
    const int warp = tid >> 5, lane = tid & 31;
    const int wm = (warp & 1) * 64;
    const int wn = (warp >> 1) * 32;

    const __half* Ab = A + (size_t)blockIdx.y * 128 * 1024;
    const __half* Bb = B + (size_t)blockIdx.x * 128 * 1024;

    float acc[4][4][4];
#pragma unroll
    for (int i = 0; i < 4; i++)
#pragma unroll
        for (int j = 0; j < 4; j++)
#pragma unroll
            for (int k = 0; k < 4; k++) acc[i][j][k] = 0.f;

    auto load_stage = [&](int v) {
        const uint32_t base = sb + (uint32_t)(v & 3) * GH_STAGE_B;
        const int kb = v * 32;
#pragma unroll
        for (int i = 0; i < 2; i++) {
            const int c = tid + i * 256;     // 0..511
            const int row = c >> 2, ch = c & 3;
            const uint32_t da = base + (uint32_t)(row * 80 + ch * 16);
            asm volatile("cp.async.cg.shared.global [%0], [%1], 16;"
                         :: "r"(da), "l"(Ab + (size_t)row * 1024 + kb + ch * 8));
            const uint32_t db = base + 10240u + (uint32_t)(row * 80 + ch * 16);
            asm volatile("cp.async.cg.shared.global [%0], [%1], 16;"
                         :: "r"(db), "l"(Bb + (size_t)row * 1024 + kb + ch * 8));
        }
    };

    load_stage(0); asm volatile("cp.async.commit_group;");
    load_stage(1); asm volatile("cp.async.commit_group;");
    load_stage(2); asm volatile("cp.async.commit_group;");

    // ldmatrix per-lane address components
    const int arow80 = (lane & 15) * 80;            // A: rows m0..m0+15
    const int asel   = (lane >> 4) * 16;            // A: k or k+8 (bytes)
    const int brow80 = ((lane & 7) + ((lane >> 4) & 1) * 8) * 80;  // B rows n
    const int bsel   = ((lane >> 3) & 1) * 16;      // B: k or k+8 (bytes)

    for (int kt = 0; kt < 32; kt++) {
        asm volatile("cp.async.wait_group 2;");
        __syncthreads();                  // stage kt resident for all threads
        if (kt + 3 < 32) load_stage(kt + 3);   // overwrites consumed slot
        asm volatile("cp.async.commit_group;");

        const uint32_t Abase = sb + (uint32_t)(kt & 3) * GH_STAGE_B;
        const uint32_t Bbase = Abase + 10240u;
#pragma unroll
        for (int ks = 0; ks < 2; ks++) {
            const int k0b = ks * 32;      // 16 halfs = 32 bytes
            uint32_t a[4][4];
#pragma unroll
            for (int am = 0; am < 4; am++) {
                const uint32_t ad = Abase +
                    (uint32_t)((wm + am * 16) * 80 + arow80 + k0b + asel);
                asm volatile(
                    "ldmatrix.sync.aligned.m8n8.x4.shared.b16 {%0,%1,%2,%3}, [%4];"
                    : "=r"(a[am][0]), "=r"(a[am][1]), "=r"(a[am][2]), "=r"(a[am][3])
                    : "r"(ad));
            }
            uint32_t b[4][2];
#pragma unroll
            for (int g = 0; g < 2; g++) {
                const uint32_t bd = Bbase +
                    (uint32_t)((wn + g * 16) * 80 + brow80 + k0b + bsel);
                uint32_t r0, r1, r2, r3;
                asm volatile(
                    "ldmatrix.sync.aligned.m8n8.x4.shared.b16 {%0,%1,%2,%3}, [%4];"
                    : "=r"(r0), "=r"(r1), "=r"(r2), "=r"(r3) : "r"(bd));
                b[2 * g][0] = r0; b[2 * g][1] = r1;
                b[2 * g + 1][0] = r2; b[2 * g + 1][1] = r3;
            }
#pragma unroll
            for (int am = 0; am < 4; am++)
#pragma unroll
                for (int bn = 0; bn < 4; bn++)
                    asm volatile(
                        "mma.sync.aligned.m16n8k16.row.col.f32.f16.f16.f32 "
                        "{%0,%1,%2,%3}, {%4,%5,%6,%7}, {%8,%9}, {%0,%1,%2,%3};"
                        : "+f"(acc[am][bn][0]), "+f"(acc[am][bn][1]),
                          "+f"(acc[am][bn][2]), "+f"(acc[am][bn][3])
                        : "r"(a[am][0]), "r"(a[am][1]), "r"(a[am][2]), "r"(a[am][3]),
                          "r"(b[bn][0]), "r"(b[bn][1]));
        }
    }

    // epilogue: bias add + float2 stores
    const int rowBase = blockIdx.y * 128 + wm + (lane >> 2);
    const int colBase = blockIdx.x * 128 + wn;
#pragma unroll
    for (int bn = 0; bn < 4; bn++) {
        const int col = colBase + bn * 8 + (lane & 3) * 2;
        const float b0 = bias[col];
        const float b1 = bias[col + 1];
#pragma unroll
        for (int am = 0; am < 4; am++) {
            const int row = rowBase + am * 16;
            float2 v;
            v.x = acc[am][bn][0] + b0;
            v.y = acc[am][bn][1] + b1;
            *(float2*)&C[(size_t)row * 1024 + col] = v;
            v.x = acc[am][bn][2] + b0;
            v.y = acc[am][bn][3] + b1;
            *(float2*)&C[(size_t)(row + 8) * 1024 + col] = v;
        }
    }
}

// ---------------------------------------------------------------------------
// smem-free head-gram attention. 2 positions per 256-thread block.
// Thread (q in 0..15, j in 0..7) owns d-slice [8j, 8j+8). Gram partials
// reduced via 3 shfl.bfly steps in the 8-lane group; softmax redundant per
// group (no barriers). Store folds the reference's scrambled flat reshape
// ((N,H,S,D)->(N,S,E): row' = q*256 + s/16, col' = (s%16)*64 + d) and
// converts to fp16 for the final GEMM.
// ---------------------------------------------------------------------------
__global__ __launch_bounds__(256)
void attn_kernel() {
    const int pos = blockIdx.x * 2 + (threadIdx.x >> 7);
    const int t = threadIdx.x & 127;
    const int s = pos & 4095;
    const int n = pos >> 12;
    const int q = t >> 3;
    const int d0 = (t & 7) * 8;

    const float* Qp = g_Q + (size_t)pos * 1024 + q * 64 + d0;
    const float* Kp = g_K + (size_t)pos * 1024 + d0;
    const float* Vp = g_V + (size_t)pos * 1024 + d0;

    const float4 qa = *(const float4*)(Qp);
    const float4 qb = *(const float4*)(Qp + 4);

    float sc[16];
#pragma unroll
    for (int l = 0; l < 16; l++) {
        const float4 ka = *(const float4*)(Kp + l * 64);
        const float4 kb = *(const float4*)(Kp + l * 64 + 4);
        float a = qa.x * ka.x;
        a = fmaf(qa.y, ka.y, a);
        a = fmaf(qa.z, ka.z, a);
        a = fmaf(qa.w, ka.w, a);
        a = fmaf(qb.x, kb.x, a);
        a = fmaf(qb.y, kb.y, a);
        a = fmaf(qb.z, kb.z, a);
        a = fmaf(qb.w, kb.w, a);
        sc[l] = a;
    }
#pragma unroll
    for (int l = 0; l < 16; l++) {
        sc[l] += __shfl_xor_sync(0xffffffffu, sc[l], 1);
        sc[l] += __shfl_xor_sync(0xffffffffu, sc[l], 2);
        sc[l] += __shfl_xor_sync(0xffffffffu, sc[l], 4);
        sc[l] *= 0.125f;  // 1/sqrt(64)
    }
    float mx = sc[0];
#pragma unroll
    for (int l = 1; l < 16; l++) mx = fmaxf(mx, sc[l]);
    float sum = 0.f;
#pragma unroll
    for (int l = 0; l < 16; l++) { sc[l] = expf(sc[l] - mx); sum += sc[l]; }
    const float inv = 1.0f / sum;

    float4 oa = {0.f, 0.f, 0.f, 0.f}, ob = {0.f, 0.f, 0.f, 0.f};
#pragma unroll
    for (int l = 0; l < 16; l++) {
        const float w = sc[l] * inv;
        const float4 va = *(const float4*)(Vp + l * 64);
        const float4 vb = *(const float4*)(Vp + l * 64 + 4);
        oa.x = fmaf(w, va.x, oa.x);
        oa.y = fmaf(w, va.y, oa.y);
        oa.z = fmaf(w, va.z, oa.z);
        oa.w = fmaf(w, va.w, oa.w);
        ob.x = fmaf(w, vb.x, ob.x);
        ob.y = fmaf(w, vb.y, ob.y);
        ob.z = fmaf(w, vb.z, ob.z);
        ob.w = fmaf(w, vb.w, ob.w);
    }

    __half2 h0 = __floats2half2_rn(oa.x, oa.y);
    __half2 h1 = __floats2half2_rn(oa.z, oa.w);
    __half2 h2 = __floats2half2_rn(ob.x, ob.y);
    __half2 h3 = __floats2half2_rn(ob.z, ob.w);
    uint4 out;
    out.x = *(uint32_t*)&h0;
    out.y = *(uint32_t*)&h1;
    out.z = *(uint32_t*)&h2;
    out.w = *(uint32_t*)&h3;

    __half* op = g_Oh + (((size_t)n << 12) + (q << 8) + (s >> 4)) * 1024
               + (s & 15) * 64 + d0;
    *(uint4*)op = out;
}

// ---------------- fp32 -> fp16 conversion ----------------------------------
__global__ __launch_bounds__(256)
void to_half_k(const float4* __restrict__ in, uint2* __restrict__ out, int n4) {
    const int i = blockIdx.x * 256 + threadIdx.x;
    if (i < n4) {
        const float4 v = in[i];
        __half2 h0 = __floats2half2_rn(v.x, v.y);
        __half2 h1 = __floats2half2_rn(v.z, v.w);
        uint2 o;
        o.x = *(uint32_t*)&h0;
        o.y = *(uint32_t*)&h1;
        out[i] = o;
    }
}

// ---------------- launch ---------------------------------------------------
extern "C" void kernel_launch(void* const* d_in, const int* in_sizes, int n_in,
                              void* d_out, int out_size) {
    const float* x  = (const float*)d_in[0];
    const float* Wq = (const float*)d_in[1];
    const float* bq = (const float*)d_in[2];
    const float* Wk = (const float*)d_in[3];
    const float* bk = (const float*)d_in[4];
    const float* Wv = (const float*)d_in[5];
    const float* bv = (const float*)d_in[6];
    const float* Wo = (const float*)d_in[7];
    const float* bo = (const float*)d_in[8];

    __half *pXh, *pWh, *pOh;
    float *pQ, *pK, *pV;
    cudaGetSymbolAddress((void**)&pXh, g_Xh);
    cudaGetSymbolAddress((void**)&pWh, g_Wh);
    cudaGetSymbolAddress((void**)&pOh, g_Oh);
    cudaGetSymbolAddress((void**)&pQ, g_Q);
    cudaGetSymbolAddress((void**)&pK, g_K);
    cudaGetSymbolAddress((void**)&pV, g_V);

    cudaFuncSetAttribute(gemm_h, cudaFuncAttributeMaxDynamicSharedMemorySize,
                         GH_SMEM);

    to_half_k<<<16384, 256>>>((const float4*)x,  (uint2*)pXh,             4194304);
    to_half_k<<<1024, 256>>>((const float4*)Wq, (uint2*)(pWh),            262144);
    to_half_k<<<1024, 256>>>((const float4*)Wk, (uint2*)(pWh + 1048576),  262144);
    to_half_k<<<1024, 256>>>((const float4*)Wv, (uint2*)(pWh + 2097152),  262144);
    to_half_k<<<1024, 256>>>((const float4*)Wo, (uint2*)(pWh + 3145728),  262144);

    dim3 grid(8, 128), blk(256);
    gemm_h<<<grid, blk, GH_SMEM>>>(pXh, pWh,           bq, pQ);
    gemm_h<<<grid, blk, GH_SMEM>>>(pXh, pWh + 1048576, bk, pK);
    gemm_h<<<grid, blk, GH_SMEM>>>(pXh, pWh + 2097152, bv, pV);
    attn_kernel<<<8192, 256>>>();
    gemm_h<<<grid, blk, GH_SMEM>>>(pOh, pWh + 3145728, bo, (float*)d_out);
}

// round 12
// speedup vs baseline: 2.2070x; 1.2349x over previous
#include <cuda_runtime.h>
#include <cuda_fp16.h>
#include <cstdint>
#include <math.h>

// N=4, S=4096, E=1024, H=16, D=64
// fused convert(x,W,bias) -> fp16 | ONE merged QKV GEMM [16384,3072] fp16-out
// | smem-free head-gram attention (fp16 in/out, scrambled store) | final GEMM
// fp32-out. Legacy HMMA path only (tcgen05 rejected at compute_103 target).

// ---------------- scratch (alloc-guard compliant device globals) ----------
__device__ __half g_Xh[16777216];      // x in fp16
__device__ __half g_QKVh[50331648];    // QKV merged output [16384,3072] fp16
__device__ __half g_Oh[16777216];      // attn out, scrambled, fp16
__device__ __half g_Wh[4194304];       // Wq,Wk,Wv,Wo in fp16 (concat)
__device__ float  g_bias[3072];        // bq|bk|bv concat

__device__ __forceinline__ uint32_t smem_u32(const void* p) {
    uint32_t a;
    asm("{ .reg .u64 t; cvta.to.shared.u64 t, %1; cvt.u32.u64 %0, t; }"
        : "=r"(a) : "l"(p));
    return a;
}

// ---------------------------------------------------------------------------
// fp16 GEMM: C[16384,NC] = Ah[16384,1024] @ Bh[NC,1024]^T + bias (fp32 acc)
// CTA tile 128x128, BK=32, 4-stage cp.async pipeline, 8 warps (2Mx4N),
// warp tile 64x32, mma.sync.m16n8k16. smem pitch 80B: 16B-aligned cp.async
// dsts AND conflict-free ldmatrix (banks (20r+c) mod 32 distinct, r in 0..7).
// ---------------------------------------------------------------------------
static constexpr int GH_STAGE_B = 20480;           // (128+128) rows * 80B
static constexpr int GH_SMEM    = 4 * GH_STAGE_B;  // 81920

template <typename OutT>
__global__ __launch_bounds__(256, 2)
void gemm_h(const __half* __restrict__ A, const __half* __restrict__ B,
            const float* __restrict__ bias, OutT* __restrict__ C, int ldc) {
    extern __shared__ __align__(128) char smem[];
    const uint32_t sb = smem_u32(smem);
    const int tid = threadIdx.x;
    const int warp = tid >> 5, lane = tid & 31;
    const int wm = (warp & 1) * 64;
    const int wn = (warp >> 1) * 32;

    const __half* Ab = A + (size_t)blockIdx.y * 128 * 1024;
    const __half* Bb = B + (size_t)blockIdx.x * 128 * 1024;

    float acc[4][4][4];
#pragma unroll
    for (int i = 0; i < 4; i++)
#pragma unroll
        for (int j = 0; j < 4; j++)
#pragma unroll
            for (int k = 0; k < 4; k++) acc[i][j][k] = 0.f;

    auto load_stage = [&](int v) {
        const uint32_t base = sb + (uint32_t)(v & 3) * GH_STAGE_B;
        const int kb = v * 32;
#pragma unroll
        for (int i = 0; i < 2; i++) {
            const int c = tid + i * 256;     // 0..511
            const int row = c >> 2, ch = c & 3;
            const uint32_t da = base + (uint32_t)(row * 80 + ch * 16);
            asm volatile("cp.async.cg.shared.global [%0], [%1], 16;"
                         :: "r"(da), "l"(Ab + (size_t)row * 1024 + kb + ch * 8));
            const uint32_t db = base + 10240u + (uint32_t)(row * 80 + ch * 16);
            asm volatile("cp.async.cg.shared.global [%0], [%1], 16;"
                         :: "r"(db), "l"(Bb + (size_t)row * 1024 + kb + ch * 8));
        }
    };

    load_stage(0); asm volatile("cp.async.commit_group;");
    load_stage(1); asm volatile("cp.async.commit_group;");
    load_stage(2); asm volatile("cp.async.commit_group;");

    // ldmatrix per-lane address components
    const int arow80 = (lane & 15) * 80;            // A rows m0..m0+15
    const int asel   = (lane >> 4) * 16;            // A: k or k+8 (bytes)
    const int brow80 = ((lane & 7) + ((lane >> 4) & 1) * 8) * 80;  // B rows n
    const int bsel   = ((lane >> 3) & 1) * 16;      // B: k or k+8 (bytes)

    for (int kt = 0; kt < 32; kt++) {
        asm volatile("cp.async.wait_group 2;");
        __syncthreads();                  // stage kt resident for all threads
        if (kt + 3 < 32) load_stage(kt + 3);
        asm volatile("cp.async.commit_group;");

        const uint32_t Abase = sb + (uint32_t)(kt & 3) * GH_STAGE_B;
        const uint32_t Bbase = Abase + 10240u;
#pragma unroll
        for (int ks = 0; ks < 2; ks++) {
            const int k0b = ks * 32;      // 16 halfs = 32 bytes
            uint32_t a[4][4];
#pragma unroll
            for (int am = 0; am < 4; am++) {
                const uint32_t ad = Abase +
                    (uint32_t)((wm + am * 16) * 80 + arow80 + k0b + asel);
                asm volatile(
                    "ldmatrix.sync.aligned.m8n8.x4.shared.b16 {%0,%1,%2,%3}, [%4];"
                    : "=r"(a[am][0]), "=r"(a[am][1]), "=r"(a[am][2]), "=r"(a[am][3])
                    : "r"(ad));
            }
            uint32_t b[4][2];
#pragma unroll
            for (int g = 0; g < 2; g++) {
                const uint32_t bd = Bbase +
                    (uint32_t)((wn + g * 16) * 80 + brow80 + k0b + bsel);
                uint32_t r0, r1, r2, r3;
                asm volatile(
                    "ldmatrix.sync.aligned.m8n8.x4.shared.b16 {%0,%1,%2,%3}, [%4];"
                    : "=r"(r0), "=r"(r1), "=r"(r2), "=r"(r3) : "r"(bd));
                b[2 * g][0] = r0; b[2 * g][1] = r1;
                b[2 * g + 1][0] = r2; b[2 * g + 1][1] = r3;
            }
#pragma unroll
            for (int am = 0; am < 4; am++)
#pragma unroll
                for (int bn = 0; bn < 4; bn++)
                    asm volatile(
                        "mma.sync.aligned.m16n8k16.row.col.f32.f16.f16.f32 "
                        "{%0,%1,%2,%3}, {%4,%5,%6,%7}, {%8,%9}, {%0,%1,%2,%3};"
                        : "+f"(acc[am][bn][0]), "+f"(acc[am][bn][1]),
                          "+f"(acc[am][bn][2]), "+f"(acc[am][bn][3])
                        : "r"(a[am][0]), "r"(a[am][1]), "r"(a[am][2]), "r"(a[am][3]),
                          "r"(b[bn][0]), "r"(b[bn][1]));
        }
    }

    // epilogue: bias add + stores (fp32 or fp16 out)
    const int rowBase = blockIdx.y * 128 + wm + (lane >> 2);
    const int colBase = blockIdx.x * 128 + wn;
#pragma unroll
    for (int bn = 0; bn < 4; bn++) {
        const int col = colBase + bn * 8 + (lane & 3) * 2;
        const float b0 = bias[col];
        const float b1 = bias[col + 1];
#pragma unroll
        for (int am = 0; am < 4; am++) {
            const int row = rowBase + am * 16;
            if constexpr (sizeof(OutT) == 4) {
                float2 v;
                v.x = acc[am][bn][0] + b0;
                v.y = acc[am][bn][1] + b1;
                *(float2*)&C[(size_t)row * ldc + col] = v;
                v.x = acc[am][bn][2] + b0;
                v.y = acc[am][bn][3] + b1;
                *(float2*)&C[(size_t)(row + 8) * ldc + col] = v;
            } else {
                __half2 h;
                h = __floats2half2_rn(acc[am][bn][0] + b0, acc[am][bn][1] + b1);
                *(__half2*)&C[(size_t)row * ldc + col] = h;
                h = __floats2half2_rn(acc[am][bn][2] + b0, acc[am][bn][3] + b1);
                *(__half2*)&C[(size_t)(row + 8) * ldc + col] = h;
            }
        }
    }
}

// ---------------------------------------------------------------------------
// smem-free head-gram attention, fp16 in (QKV merged rows of 3072) / fp16 out.
// 2 positions per 256-thread block; thread (q in 0..15, j in 0..7) owns
// d-slice [8j,8j+8). Gram reduced via 3 shfl.bfly steps in 8-lane group;
// softmax redundant per group (no barriers). Store folds scrambled reshape
// row' = q*256 + s/16, col' = (s%16)*64 + d.
// ---------------------------------------------------------------------------
__device__ __forceinline__ void h8_to_f(const __half* p, float* f) {
    const uint4 u = *(const uint4*)p;
    float2 t;
    t = __half22float2(*(const __half2*)&u.x); f[0] = t.x; f[1] = t.y;
    t = __half22float2(*(const __half2*)&u.y); f[2] = t.x; f[3] = t.y;
    t = __half22float2(*(const __half2*)&u.z); f[4] = t.x; f[5] = t.y;
    t = __half22float2(*(const __half2*)&u.w); f[6] = t.x; f[7] = t.y;
}

__global__ __launch_bounds__(256)
void attn_kernel() {
    const int pos = blockIdx.x * 2 + (threadIdx.x >> 7);
    const int t = threadIdx.x & 127;
    const int s = pos & 4095;
    const int n = pos >> 12;
    const int q = t >> 3;
    const int d0 = (t & 7) * 8;

    const __half* base = g_QKVh + (size_t)pos * 3072;
    const __half* Qp = base + q * 64 + d0;
    const __half* Kp = base + 1024 + d0;
    const __half* Vp = base + 2048 + d0;

    float qf[8];
    h8_to_f(Qp, qf);

    float sc[16];
#pragma unroll
    for (int l = 0; l < 16; l++) {
        float kf[8];
        h8_to_f(Kp + l * 64, kf);
        float a = qf[0] * kf[0];
#pragma unroll
        for (int j = 1; j < 8; j++) a = fmaf(qf[j], kf[j], a);
        sc[l] = a;
    }
#pragma unroll
    for (int l = 0; l < 16; l++) {
        sc[l] += __shfl_xor_sync(0xffffffffu, sc[l], 1);
        sc[l] += __shfl_xor_sync(0xffffffffu, sc[l], 2);
        sc[l] += __shfl_xor_sync(0xffffffffu, sc[l], 4);
        sc[l] *= 0.125f;  // 1/sqrt(64)
    }
    float mx = sc[0];
#pragma unroll
    for (int l = 1; l < 16; l++) mx = fmaxf(mx, sc[l]);
    float sum = 0.f;
#pragma unroll
    for (int l = 0; l < 16; l++) { sc[l] = __expf(sc[l] - mx); sum += sc[l]; }
    const float inv = 1.0f / sum;

    float o[8];
#pragma unroll
    for (int j = 0; j < 8; j++) o[j] = 0.f;
#pragma unroll
    for (int l = 0; l < 16; l++) {
        const float w = sc[l] * inv;
        float vf[8];
        h8_to_f(Vp + l * 64, vf);
#pragma unroll
        for (int j = 0; j < 8; j++) o[j] = fmaf(w, vf[j], o[j]);
    }

    __half2 h0 = __floats2half2_rn(o[0], o[1]);
    __half2 h1 = __floats2half2_rn(o[2], o[3]);
    __half2 h2 = __floats2half2_rn(o[4], o[5]);
    __half2 h3 = __floats2half2_rn(o[6], o[7]);
    uint4 out;
    out.x = *(uint32_t*)&h0;
    out.y = *(uint32_t*)&h1;
    out.z = *(uint32_t*)&h2;
    out.w = *(uint32_t*)&h3;

    __half* op = g_Oh + (((size_t)n << 12) + (q << 8) + (s >> 4)) * 1024
               + (s & 15) * 64 + d0;
    *(uint4*)op = out;
}

// ---------------- fused conversion: x + 4 weights + bias concat ------------
__global__ __launch_bounds__(256)
void conv_fused(const float4* __restrict__ x,
                const float4* __restrict__ wq, const float4* __restrict__ wk,
                const float4* __restrict__ wv, const float4* __restrict__ wo,
                const float4* __restrict__ bq, const float4* __restrict__ bk,
                const float4* __restrict__ bv) {
    const int i = blockIdx.x * 256 + threadIdx.x;
    float4 v;
    uint2* dst;
    if (i < 4194304) {
        v = x[i];
        dst = (uint2*)g_Xh + i;
    } else {
        const int w = i - 4194304;           // 0..1048575
        const int seg = w >> 18;             // 0..3
        const int off = w & 262143;
        v = (seg == 0) ? wq[off] : (seg == 1) ? wk[off]
          : (seg == 2) ? wv[off] : wo[off];
        dst = (uint2*)g_Wh + w;
    }
    __half2 h0 = __floats2half2_rn(v.x, v.y);
    __half2 h1 = __floats2half2_rn(v.z, v.w);
    uint2 o;
    o.x = *(uint32_t*)&h0;
    o.y = *(uint32_t*)&h1;
    *dst = o;

    if (i < 768) {  // bias concat (3072 floats = 768 float4)
        float4 b = (i < 256) ? bq[i] : (i < 512) ? bk[i - 256] : bv[i - 512];
        ((float4*)g_bias)[i] = b;
    }
}

// ---------------- launch ---------------------------------------------------
extern "C" void kernel_launch(void* const* d_in, const int* in_sizes, int n_in,
                              void* d_out, int out_size) {
    const float* x  = (const float*)d_in[0];
    const float* Wq = (const float*)d_in[1];
    const float* bq = (const float*)d_in[2];
    const float* Wk = (const float*)d_in[3];
    const float* bk = (const float*)d_in[4];
    const float* Wv = (const float*)d_in[5];
    const float* bv = (const float*)d_in[6];
    const float* Wo = (const float*)d_in[7];
    const float* bo = (const float*)d_in[8];

    __half *pXh, *pWh, *pOh, *pQKV;
    float *pBias;
    cudaGetSymbolAddress((void**)&pXh,  g_Xh);
    cudaGetSymbolAddress((void**)&pWh,  g_Wh);
    cudaGetSymbolAddress((void**)&pOh,  g_Oh);
    cudaGetSymbolAddress((void**)&pQKV, g_QKVh);
    cudaGetSymbolAddress((void**)&pBias, g_bias);

    cudaFuncSetAttribute(gemm_h<__half>,
                         cudaFuncAttributeMaxDynamicSharedMemorySize, GH_SMEM);
    cudaFuncSetAttribute(gemm_h<float>,
                         cudaFuncAttributeMaxDynamicSharedMemorySize, GH_SMEM);

    conv_fused<<<20480, 256>>>((const float4*)x,
                               (const float4*)Wq, (const float4*)Wk,
                               (const float4*)Wv, (const float4*)Wo,
                               (const float4*)bq, (const float4*)bk,
                               (const float4*)bv);

    // merged QKV GEMM: C[16384,3072] fp16
    gemm_h<__half><<<dim3(24, 128), 256, GH_SMEM>>>(pXh, pWh, pBias, pQKV, 3072);
    attn_kernel<<<8192, 256>>>();
    // final GEMM: fp32 out
    gemm_h<float><<<dim3(8, 128), 256, GH_SMEM>>>(pOh, pWh + 3145728, bo,
                                                  (float*)d_out, 1024);
}